// round 5
// baseline (speedup 1.0000x reference)
#include <cuda_runtime.h>
#include <cuda_bf16.h>
#include <cstddef>

#define BB 4096
#define DD 128
#define KK 32768
#define HH 3
#define NSPLIT 4
#define TM 16                 // rows per block
#define NW 4                  // warps per block
#define KS (KK / NSPLIT)      // 8192 codes per split
#define TILES (KS / 32)       // 256 tiles of 32 codes

// Scratch (device globals: no allocation allowed in kernel_launch)
__device__ float g_resid[BB * DD];
__device__ float g_quant[BB * DD];
__device__ float g_rn[BB];
__device__ float g_wn[HH * KK];
__device__ float g_best[NSPLIT * BB];
__device__ int   g_bidx[NSPLIT * BB];
__device__ int   g_codes[BB * HH];

__global__ void init_k(const float* __restrict__ in) {
    int i = blockIdx.x * blockDim.x + threadIdx.x;
    if (i < BB * DD) {
        g_resid[i] = in[i];
        g_quant[i] = 0.0f;
    }
}

// XLA-style row sum-of-squares over 128 elements:
// separate square rounding, lane-strided sequential partials, shfl-down tree.
__device__ __forceinline__ float row_sumsq_xla(const float* __restrict__ base,
                                               int lane) {
    float a =            __fmul_rn(base[lane],      base[lane]);
    a = __fadd_rn(a,     __fmul_rn(base[lane + 32], base[lane + 32]));
    a = __fadd_rn(a,     __fmul_rn(base[lane + 64], base[lane + 64]));
    a = __fadd_rn(a,     __fmul_rn(base[lane + 96], base[lane + 96]));
#pragma unroll
    for (int off = 16; off; off >>= 1)
        a = __fadd_rn(a, __shfl_down_sync(0xffffffffu, a, off));
    return a;  // valid in lane 0
}

// rn = sum(resid^2, axis=1): one warp per row.
__global__ void rn_k() {
    const int warp = threadIdx.x >> 5, lane = threadIdx.x & 31;
    const int row = blockIdx.x * 8 + warp;
    float a = row_sumsq_xla(g_resid + (size_t)row * DD, lane);
    if (lane == 0) g_rn[row] = a;
}

// wn = sum(W^2, axis=1) for all heads: one warp per codeword.
__global__ void wn_k(const float* __restrict__ emb) {
    const int warp = threadIdx.x >> 5, lane = threadIdx.x & 31;
    const int code = blockIdx.x * 8 + warp;
    if (code >= HH * KK) return;
    float a = row_sumsq_xla(emb + (size_t)code * DD, lane);
    if (lane == 0) g_wn[code] = a;
}

// Fused score + running argmax.
// Score replicates the reference bit pattern:
//   s = -( (rn + wn_c) - 2*dot_c ),  dot_c = sequential fp32 FMA chain over k
// dot chains use fma.rn.f32x2 (two rows per 64-bit acc) — bit-exact per half.
__global__ void __launch_bounds__(128) score_k(const float* __restrict__ emb,
                                               int head) {
    __shared__ float sres[DD][TM];   // transposed residual tile
    __shared__ float srn[TM];
    __shared__ float sbest[NW][TM];
    __shared__ int   sbidx[NW][TM];

    const int tid  = threadIdx.x;
    const int lane = tid & 31;
    const int warp = tid >> 5;
    const int row0 = blockIdx.x * TM;
    const int c0   = blockIdx.y * KS;

    for (int idx = tid; idx < TM * DD; idx += 128) {
        int m = idx >> 7;         // idx / DD
        int k = idx & (DD - 1);   // idx % DD
        sres[k][m] = g_resid[(size_t)(row0 + m) * DD + k];
    }
    if (tid < TM) srn[tid] = g_rn[row0 + tid];
    __syncthreads();

    const float* __restrict__ Wbase  = emb + (size_t)head * KK * DD;
    const float* __restrict__ wnbase = g_wn + head * KK;

    float bs[TM];
    int   bi[TM];
#pragma unroll
    for (int m = 0; m < TM; m++) { bs[m] = -3.4e38f; bi[m] = 0x7fffffff; }

    for (int t = warp; t < TILES; t += NW) {
        const int c = c0 + t * 32 + lane;
        const float4* __restrict__ wp = (const float4*)(Wbase + (size_t)c * DD);
        const float wn = __ldg(&wnbase[c]);

        unsigned long long acc[8];
#pragma unroll
        for (int p = 0; p < 8; p++) acc[p] = 0ull;

#pragma unroll 1
        for (int h2 = 0; h2 < 2; h2++) {          // two K-halves, order preserved
            float4 Wr[16];
#pragma unroll
            for (int i = 0; i < 16; i++) Wr[i] = __ldg(&wp[h2 * 16 + i]);
#pragma unroll
            for (int i = 0; i < 16; i++) {
                const int kb = h2 * 64 + i * 4;
                const float wv[4] = {Wr[i].x, Wr[i].y, Wr[i].z, Wr[i].w};
#pragma unroll
                for (int j = 0; j < 4; j++) {
                    unsigned long long wd;
                    asm("mov.b64 %0, {%1, %1};" : "=l"(wd) : "f"(wv[j]));
                    const float* rr = &sres[kb + j][0];
#pragma unroll
                    for (int g = 0; g < 4; g++) {
                        ulonglong2 r2 =
                            *reinterpret_cast<const ulonglong2*>(rr + 4 * g);
                        asm("fma.rn.f32x2 %0, %1, %2, %0;"
                            : "+l"(acc[2 * g]) : "l"(wd), "l"(r2.x));
                        asm("fma.rn.f32x2 %0, %1, %2, %0;"
                            : "+l"(acc[2 * g + 1]) : "l"(wd), "l"(r2.y));
                    }
                }
            }
        }

        // Score 16 rows: s = -((rn + wn) - 2*dot), strict > keeps lowest c.
#pragma unroll
        for (int p = 0; p < 8; p++) {
            float d0, d1;
            asm("mov.b64 {%0, %1}, %2;" : "=f"(d0), "=f"(d1) : "l"(acc[p]));
            {
                float t1 = __fadd_rn(srn[2 * p], wn);
                float s  = -__fsub_rn(t1, __fmul_rn(2.0f, d0));
                if (s > bs[2 * p]) { bs[2 * p] = s; bi[2 * p] = c; }
            }
            {
                float t1 = __fadd_rn(srn[2 * p + 1], wn);
                float s  = -__fsub_rn(t1, __fmul_rn(2.0f, d1));
                if (s > bs[2 * p + 1]) { bs[2 * p + 1] = s; bi[2 * p + 1] = c; }
            }
        }
    }

    // Per-warp argmax reduce for each row (value desc, index asc on ties).
#pragma unroll
    for (int m = 0; m < TM; m++) {
        float s = bs[m];
        int idx = bi[m];
#pragma unroll
        for (int off = 16; off; off >>= 1) {
            float os = __shfl_down_sync(0xffffffffu, s, off);
            int   oi = __shfl_down_sync(0xffffffffu, idx, off);
            if (os > s || (os == s && oi < idx)) { s = os; idx = oi; }
        }
        if (lane == 0) { sbest[warp][m] = s; sbidx[warp][m] = idx; }
    }
    __syncthreads();

    if (tid < TM) {
        float s = sbest[0][tid];
        int idx = sbidx[0][tid];
#pragma unroll
        for (int w = 1; w < NW; w++) {
            float os = sbest[w][tid];
            int   oi = sbidx[w][tid];
            if (os > s || (os == s && oi < idx)) { s = os; idx = oi; }
        }
        g_best[blockIdx.y * BB + row0 + tid] = s;
        g_bidx[blockIdx.y * BB + row0 + tid] = idx;
    }
}

// Merge the NSPLIT partial argmaxes, apply residual/quant update, record code.
__global__ void update_k(const float* __restrict__ emb, int head) {
    const int b = blockIdx.x;
    const int d = threadIdx.x;

    float s = g_best[b];
    int idx = g_bidx[b];
#pragma unroll
    for (int sp = 1; sp < NSPLIT; sp++) {
        float os = g_best[sp * BB + b];
        int   oi = g_bidx[sp * BB + b];
        if (os > s || (os == s && oi < idx)) { s = os; idx = oi; }
    }

    const float w = emb[(size_t)head * KK * DD + (size_t)idx * DD + d];
    g_resid[b * DD + d] -= w;   // single sub.f32, matches reference exactly
    g_quant[b * DD + d] += w;   // single add.f32
    if (d == 0) g_codes[b * HH + head] = idx;
}

__global__ void write_k(float* __restrict__ out,
                        int loss_off, int quant_off, int codes_off) {
    int i = blockIdx.x * blockDim.x + threadIdx.x;
    if (loss_off >= 0 && i < BB) out[loss_off + i] = 0.0f;
    if (quant_off >= 0 && i < BB * DD) out[quant_off + i] = g_quant[i];
    if (codes_off >= 0 && i < BB * HH) out[codes_off + i] = (float)g_codes[i];
}

extern "C" void kernel_launch(void* const* d_in, const int* in_sizes, int n_in,
                              void* d_out, int out_size) {
    const float* inputs = nullptr;
    const float* emb = nullptr;
    for (int i = 0; i < n_in; i++) {
        if (in_sizes[i] == BB * DD) inputs = (const float*)d_in[i];
        else if (in_sizes[i] == HH * KK * DD) emb = (const float*)d_in[i];
    }
    if (!inputs || !emb) {
        inputs = (const float*)d_in[0];
        emb = (const float*)d_in[1];
    }

    init_k<<<(BB * DD + 255) / 256, 256>>>(inputs);
    wn_k<<<(HH * KK) / 8, 256>>>(emb);

    for (int h = 0; h < HH; h++) {
        rn_k<<<BB / 8, 256>>>();
        dim3 grid(BB / TM, NSPLIT);
        score_k<<<grid, 128>>>(emb, h);
        update_k<<<BB, DD>>>(emb, h);
    }

    // Output layout: (loss[B], quantized[B*1*D], codes[B*H]) concatenated.
    int loss_off = -1, quant_off = -1, codes_off = -1;
    if (out_size == BB + BB * DD + BB * HH) {
        loss_off = 0; quant_off = BB; codes_off = BB + BB * DD;
    } else if (out_size == BB * DD) {
        quant_off = 0;
    } else if (out_size == BB * DD + BB * HH) {
        quant_off = 0; codes_off = BB * DD;
    } else if (out_size == BB + BB * DD) {
        loss_off = 0; quant_off = BB;
    } else {
        quant_off = 0;
    }

    write_k<<<(BB * DD + 255) / 256, 256>>>((float*)d_out,
                                            loss_off, quant_off, codes_off);
}

// round 7
// speedup vs baseline: 1.4149x; 1.4149x over previous
#include <cuda_runtime.h>
#include <cuda_bf16.h>
#include <cstddef>

#define BB 4096
#define DD 128
#define KK 32768
#define HH 3
#define NSPLIT 8
#define TM 64                 // rows per block
#define TN 128                // codes per tile
#define KCH 32                // k-depth per staged W chunk
#define NCH (DD / KCH)        // 4 chunks
#define KS (KK / NSPLIT)      // 4096 codes per split
#define NTILES (KS / TN)      // 32 tiles per block

// Scratch (device globals: no allocation allowed in kernel_launch)
__device__ float g_resid[BB * DD];
__device__ float g_quant[BB * DD];
__device__ float g_rn[BB];
__device__ float g_wn[HH * KK];
__device__ float g_best[NSPLIT * BB];
__device__ int   g_bidx[NSPLIT * BB];
__device__ int   g_codes[BB * HH];

#define DUP64(dst, f)  asm("mov.b64 %0, {%1, %1};" : "=l"(dst) : "f"(f))
#define FMA2(a, w, r)  asm("fma.rn.f32x2 %0, %1, %2, %0;" : "+l"(a) : "l"(w), "l"(r))
#define UNPK(d0, d1, a) asm("mov.b64 {%0, %1}, %2;" : "=f"(d0), "=f"(d1) : "l"(a))

__global__ void init_k(const float* __restrict__ in) {
    int i = blockIdx.x * blockDim.x + threadIdx.x;
    if (i < BB * DD) {
        g_resid[i] = in[i];
        g_quant[i] = 0.0f;
    }
}

// XLA-style row sum-of-squares over 128 elements:
// separate square rounding, lane-strided sequential partials, shfl-down tree.
__device__ __forceinline__ float row_sumsq_xla(const float* __restrict__ base,
                                               int lane) {
    float a =            __fmul_rn(base[lane],      base[lane]);
    a = __fadd_rn(a,     __fmul_rn(base[lane + 32], base[lane + 32]));
    a = __fadd_rn(a,     __fmul_rn(base[lane + 64], base[lane + 64]));
    a = __fadd_rn(a,     __fmul_rn(base[lane + 96], base[lane + 96]));
#pragma unroll
    for (int off = 16; off; off >>= 1)
        a = __fadd_rn(a, __shfl_down_sync(0xffffffffu, a, off));
    return a;  // valid in lane 0
}

__global__ void rn_k() {
    const int warp = threadIdx.x >> 5, lane = threadIdx.x & 31;
    const int row = blockIdx.x * 8 + warp;
    float a = row_sumsq_xla(g_resid + (size_t)row * DD, lane);
    if (lane == 0) g_rn[row] = a;
}

__global__ void wn_k(const float* __restrict__ emb) {
    const int warp = threadIdx.x >> 5, lane = threadIdx.x & 31;
    const int code = blockIdx.x * 8 + warp;
    if (code >= HH * KK) return;
    float a = row_sumsq_xla(emb + (size_t)code * DD, lane);
    if (lane == 0) g_wn[code] = a;
}

// Smem-staged register-tiled score + argmax.
// Block tile: TM=64 rows x TN=128 codes. 128 threads; each owns 8 rows x 8
// codes. Rows per thread: {ry*4+0..3} U {32+ry*4+0..3}; codes per thread:
// {cx*4+0..3} U {64+cx*4+0..3} (z-split -> conflict-free LDS.128).
// Per output: dot = sequential fp32 FMA chain over k=0..127 (fma.rn.f32x2,
// rows packed in pairs) -> bit-identical to reference accumulation.
// Score: s = -((rn + wn) - 2*dot); strict > keeps lowest code index.
__global__ void __launch_bounds__(128) score_k(const float* __restrict__ emb,
                                               int head) {
    __shared__ float rsm[DD * TM];     // [k][row]      32KB
    __shared__ float wsm[KCH * TN];    // [k_loc][code] 16KB

    const int tid   = threadIdx.x;
    const int cx    = tid & 15;        // code group 0..15
    const int ry    = tid >> 4;        // row group 0..7
    const int row0  = blockIdx.x * TM;
    const int split = blockIdx.y;
    const int c0b   = split * KS;

    // Stage residual tile transposed: rsm[k][row]
    {
        const float4* __restrict__ R4 = (const float4*)g_resid;
#pragma unroll
        for (int i = 0; i < 16; i++) {
            int row = (tid >> 2) + (i & 1) * 32;
            int k4  = (tid & 3) + (i >> 1) * 4;
            float4 v = R4[(size_t)(row0 + row) * 32 + k4];
            rsm[(4 * k4 + 0) * TM + row] = v.x;
            rsm[(4 * k4 + 1) * TM + row] = v.y;
            rsm[(4 * k4 + 2) * TM + row] = v.z;
            rsm[(4 * k4 + 3) * TM + row] = v.w;
        }
    }

    float rnv[8];
#pragma unroll
    for (int r = 0; r < 8; r++) {
        int row = (r < 4) ? (ry * 4 + r) : (32 + ry * 4 + (r - 4));
        rnv[r] = g_rn[row0 + row];
    }

    const float4* __restrict__ W4 =
        (const float4*)(emb + (size_t)head * KK * DD);
    const float* __restrict__ wnbase = g_wn + head * KK;

    float bs[8];
    int   bi[8];
#pragma unroll
    for (int r = 0; r < 8; r++) { bs[r] = -3.4e38f; bi[r] = 0x7fffffff; }

    for (int tile = 0; tile < NTILES; tile++) {
        const int c0 = c0b + tile * TN;

        unsigned long long acc[4][8];   // [row_pair][code]
#pragma unroll
        for (int p = 0; p < 4; p++)
#pragma unroll
            for (int c = 0; c < 8; c++) acc[p][c] = 0ull;

#pragma unroll 1
        for (int ch = 0; ch < NCH; ch++) {
            __syncthreads();   // previous compute done before wsm overwrite
            // Stage W chunk: thread tid stages code tid (one full 128B line)
            {
                const float4* __restrict__ wp =
                    W4 + (size_t)(c0 + tid) * 32 + ch * 8;
#pragma unroll
                for (int i = 0; i < 8; i++) {
                    float4 v = __ldg(&wp[i]);
                    wsm[(4 * i + 0) * TN + tid] = v.x;
                    wsm[(4 * i + 1) * TN + tid] = v.y;
                    wsm[(4 * i + 2) * TN + tid] = v.z;
                    wsm[(4 * i + 3) * TN + tid] = v.w;
                }
            }
            __syncthreads();

            const float* __restrict__ rbase = rsm + (ch * KCH) * TM + ry * 4;
#pragma unroll 4
            for (int kk = 0; kk < KCH; kk++) {
                ulonglong2 rA = *(const ulonglong2*)(rbase + kk * TM);
                ulonglong2 rB = *(const ulonglong2*)(rbase + kk * TM + 32);
                unsigned long long rp[4] = {rA.x, rA.y, rB.x, rB.y};

                const float* __restrict__ wpk = wsm + kk * TN + cx * 4;
                float4 wlo = *(const float4*)wpk;
                float4 whi = *(const float4*)(wpk + 64);
                unsigned long long wd[8];
                DUP64(wd[0], wlo.x); DUP64(wd[1], wlo.y);
                DUP64(wd[2], wlo.z); DUP64(wd[3], wlo.w);
                DUP64(wd[4], whi.x); DUP64(wd[5], whi.y);
                DUP64(wd[6], whi.z); DUP64(wd[7], whi.w);

#pragma unroll
                for (int p = 0; p < 4; p++) {
#pragma unroll
                    for (int c = 0; c < 8; c++) FMA2(acc[p][c], wd[c], rp[p]);
                }
            }
        }

        // Epilogue: 8 rows x 8 codes; codes ascend within each row (strict >
        // keeps the lowest index, matching jnp.argmax).
        float4 wna = __ldg((const float4*)&wnbase[c0 + cx * 4]);
        float4 wnb = __ldg((const float4*)&wnbase[c0 + 64 + cx * 4]);
        const float wnv[8] = {wna.x, wna.y, wna.z, wna.w,
                              wnb.x, wnb.y, wnb.z, wnb.w};
        int codev[8];
#pragma unroll
        for (int c = 0; c < 8; c++)
            codev[c] = (c < 4) ? (c0 + cx * 4 + c) : (c0 + 64 + cx * 4 + (c - 4));

#pragma unroll
        for (int p = 0; p < 4; p++) {
            const int r0 = 2 * p;   // bs index of even row of this pair
#pragma unroll
            for (int c = 0; c < 8; c++) {
                float d0, d1;
                UNPK(d0, d1, acc[p][c]);
                {
                    float t1 = __fadd_rn(rnv[r0], wnv[c]);
                    float s  = -__fsub_rn(t1, __fmul_rn(2.0f, d0));
                    if (s > bs[r0]) { bs[r0] = s; bi[r0] = codev[c]; }
                }
                {
                    float t1 = __fadd_rn(rnv[r0 + 1], wnv[c]);
                    float s  = -__fsub_rn(t1, __fmul_rn(2.0f, d1));
                    if (s > bs[r0 + 1]) { bs[r0 + 1] = s; bi[r0 + 1] = codev[c]; }
                }
            }
        }
    }

    // Cross-lane argmax within each 16-lane code group (each row owned by one
    // warp -> pure shfl reduction).
#pragma unroll
    for (int r = 0; r < 8; r++) {
        float s = bs[r];
        int idx = bi[r];
#pragma unroll
        for (int off = 8; off; off >>= 1) {
            float os = __shfl_xor_sync(0xffffffffu, s, off);
            int   oi = __shfl_xor_sync(0xffffffffu, idx, off);
            if (os > s || (os == s && oi < idx)) { s = os; idx = oi; }
        }
        if (cx == 0) {
            int row = (r < 4) ? (ry * 4 + r) : (32 + ry * 4 + (r - 4));
            g_best[split * BB + row0 + row] = s;
            g_bidx[split * BB + row0 + row] = idx;
        }
    }
}

// Merge the NSPLIT partial argmaxes, apply residual/quant update, record code.
__global__ void update_k(const float* __restrict__ emb, int head) {
    const int b = blockIdx.x;
    const int d = threadIdx.x;

    float s = g_best[b];
    int idx = g_bidx[b];
#pragma unroll
    for (int sp = 1; sp < NSPLIT; sp++) {
        float os = g_best[sp * BB + b];
        int   oi = g_bidx[sp * BB + b];
        if (os > s || (os == s && oi < idx)) { s = os; idx = oi; }
    }

    const float w = emb[(size_t)head * KK * DD + (size_t)idx * DD + d];
    g_resid[b * DD + d] -= w;   // single sub.f32, matches reference exactly
    g_quant[b * DD + d] += w;   // single add.f32
    if (d == 0) g_codes[b * HH + head] = idx;
}

__global__ void write_k(float* __restrict__ out,
                        int loss_off, int quant_off, int codes_off) {
    int i = blockIdx.x * blockDim.x + threadIdx.x;
    if (loss_off >= 0 && i < BB) out[loss_off + i] = 0.0f;
    if (quant_off >= 0 && i < BB * DD) out[quant_off + i] = g_quant[i];
    if (codes_off >= 0 && i < BB * HH) out[codes_off + i] = (float)g_codes[i];
}

extern "C" void kernel_launch(void* const* d_in, const int* in_sizes, int n_in,
                              void* d_out, int out_size) {
    const float* inputs = nullptr;
    const float* emb = nullptr;
    for (int i = 0; i < n_in; i++) {
        if (in_sizes[i] == BB * DD) inputs = (const float*)d_in[i];
        else if (in_sizes[i] == HH * KK * DD) emb = (const float*)d_in[i];
    }
    if (!inputs || !emb) {
        inputs = (const float*)d_in[0];
        emb = (const float*)d_in[1];
    }

    init_k<<<(BB * DD + 255) / 256, 256>>>(inputs);
    wn_k<<<(HH * KK) / 8, 256>>>(emb);

    for (int h = 0; h < HH; h++) {
        rn_k<<<BB / 8, 256>>>();
        dim3 grid(BB / TM, NSPLIT);
        score_k<<<grid, 128>>>(emb, h);
        update_k<<<BB, DD>>>(emb, h);
    }

    // Output layout: (loss[B], quantized[B*1*D], codes[B*H]) concatenated.
    int loss_off = -1, quant_off = -1, codes_off = -1;
    if (out_size == BB + BB * DD + BB * HH) {
        loss_off = 0; quant_off = BB; codes_off = BB + BB * DD;
    } else if (out_size == BB * DD) {
        quant_off = 0;
    } else if (out_size == BB * DD + BB * HH) {
        quant_off = 0; codes_off = BB * DD;
    } else if (out_size == BB + BB * DD) {
        loss_off = 0; quant_off = BB;
    } else {
        quant_off = 0;
    }

    write_k<<<(BB * DD + 255) / 256, 256>>>((float*)d_out,
                                            loss_off, quant_off, codes_off);
}

// round 11
// speedup vs baseline: 2.5782x; 1.8221x over previous
#include <cuda_runtime.h>
#include <cuda_bf16.h>
#include <cstddef>
#include <cstdint>

#define BB 4096
#define DD 128
#define KK 32768
#define HH 3
#define CAP 512
#define NCSPLIT 4
#define TILEN 64
#define NTILES (KK / NCSPLIT / TILEN)   // 128 tiles per CTA
#define ROWTILES (BB / 128)             // 32

// ---- device scratch (no allocation allowed) ----
__device__ float g_resid[BB * DD];
__device__ float g_quant[BB * DD];
__device__ float g_rn[BB];
__device__ float g_wn[HH * KK];
__device__ int   g_wnmaxbits[HH];
__device__ __nv_bfloat16 g_rbf[BB * DD];
__device__ __nv_bfloat16 g_wbf[HH * KK * DD];
__device__ int   g_ccnt[BB];
__device__ int   g_cand[BB * CAP];
__device__ int   g_sel[BB];
__device__ int   g_codes[BB * HH];

#define SW128(x) ((x) ^ (((x) >> 3) & 0x70))

__device__ __forceinline__ uint32_t smem_u32(const void* p) {
    uint32_t a;
    asm("{ .reg .u64 t; cvta.to.shared.u64 t, %1; cvt.u32.u64 %0, t; }"
        : "=r"(a) : "l"(p));
    return a;
}

#define LDMX4(r0, r1, r2, r3, a) \
    asm volatile("ldmatrix.sync.aligned.m8n8.x4.shared.b16 {%0,%1,%2,%3}, [%4];" \
                 : "=r"(r0), "=r"(r1), "=r"(r2), "=r"(r3) : "r"(a))

#define MMA16816(c, av, b0, b1) \
    asm volatile("mma.sync.aligned.m16n8k16.row.col.f32.bf16.bf16.f32 " \
                 "{%0,%1,%2,%3}, {%4,%5,%6,%7}, {%8,%9}, {%0,%1,%2,%3};" \
                 : "+f"((c)[0]), "+f"((c)[1]), "+f"((c)[2]), "+f"((c)[3]) \
                 : "r"((av)[0]), "r"((av)[1]), "r"((av)[2]), "r"((av)[3]), \
                   "r"(b0), "r"(b1))

// ---- small kernels ----
__global__ void init_k(const float* __restrict__ in) {
    int i = blockIdx.x * blockDim.x + threadIdx.x;
    if (i < BB * DD) { g_resid[i] = in[i]; g_quant[i] = 0.0f; }
    if (i < HH) g_wnmaxbits[i] = 0;
}

__device__ __forceinline__ float row_sumsq_xla(const float* __restrict__ base,
                                               int lane) {
    float a =        __fmul_rn(base[lane],      base[lane]);
    a = __fadd_rn(a, __fmul_rn(base[lane + 32], base[lane + 32]));
    a = __fadd_rn(a, __fmul_rn(base[lane + 64], base[lane + 64]));
    a = __fadd_rn(a, __fmul_rn(base[lane + 96], base[lane + 96]));
#pragma unroll
    for (int off = 16; off; off >>= 1)
        a = __fadd_rn(a, __shfl_down_sync(0xffffffffu, a, off));
    return a;
}

__global__ void rn_k() {
    const int warp = threadIdx.x >> 5, lane = threadIdx.x & 31;
    const int row = blockIdx.x * 8 + warp;
    float a = row_sumsq_xla(g_resid + (size_t)row * DD, lane);
    if (lane == 0) g_rn[row] = a;
}

__global__ void wn_k(const float* __restrict__ emb) {
    const int warp = threadIdx.x >> 5, lane = threadIdx.x & 31;
    const int code = blockIdx.x * 8 + warp;
    if (code >= HH * KK) return;
    float a = row_sumsq_xla(emb + (size_t)code * DD, lane);
    if (lane == 0) {
        g_wn[code] = a;
        atomicMax(&g_wnmaxbits[code >> 15], __float_as_int(a));
    }
}

__global__ void wconv_k(const float* __restrict__ emb) {
    int i = blockIdx.x * blockDim.x + threadIdx.x;
    if (i < HH * KK * DD) g_wbf[i] = __float2bfloat16_rn(emb[i]);
}

__global__ void bconv_k() {
    int i = blockIdx.x * blockDim.x + threadIdx.x;
    if (i < BB * DD) g_rbf[i] = __float2bfloat16_rn(g_resid[i]);
    if (i < BB) g_ccnt[i] = 0;
}

// ---- mma.sync bf16 approximate scorer + candidate collection ----
// CTA: 128 rows x 64-code tiles over KK/NCSPLIT codes. 8 warps; warp tile =
// 32 rows (2 m16 blocks) x 32 codes (4 n8 blocks); K=128 in 8 k16 steps.
// A smem: [2 kblk][128 rows][64 bf16] SW128 (32KB, staged once).
// B smem: [2 kblk][64 codes][64 bf16] SW128 (16KB, staged per tile).
// Candidate rule: keep code if 2*d - wn >= runmax - delta, where delta >= 2x
// the bf16 conversion error bound -> true argmax provably retained.
__global__ void __launch_bounds__(256) mma_score_k(int head) {
    __shared__ __nv_bfloat16 As[2 * 128 * 64];   // 32KB
    __shared__ __nv_bfloat16 Bs[2 * 64 * 64];    // 16KB

    const uint32_t saddrA = smem_u32(As);
    const uint32_t saddrB = smem_u32(Bs);
    const int tid  = threadIdx.x;
    const int wid  = tid >> 5;
    const int lane = tid & 31;
    const int rowblk = wid & 3;        // 32-row group
    const int cg     = wid >> 2;       // 32-code group (0..1)
    const int rowtile = blockIdx.x;
    const int split   = blockIdx.y;

    // ---- stage A once ----
    {
        const int row = tid >> 1, half = tid & 1;
        const uint4* src = (const uint4*)(g_rbf
            + (size_t)(rowtile * 128 + row) * DD + half * 64);
        char* dstb = (char*)As + half * 16384;
#pragma unroll
        for (int i = 0; i < 8; i++) {
            uint32_t x = (uint32_t)(row * 128 + i * 16);
            *(uint4*)(dstb + SW128(x)) = src[i];
        }
    }

    // Per-lane rows: mb in {0,1} x rowpart in {0,8}: 4 rows.
    const int gid = lane >> 2, tig = lane & 3;
    int   grow[4];
    float runmax[4], delta[4];
    {
        float wmax = __int_as_float(g_wnmaxbits[head]);
        float sw = sqrtf(wmax);
#pragma unroll
        for (int q = 0; q < 4; q++) {
            int rl = (q >> 1) * 16 + gid + (q & 1) * 8;
            grow[q] = rowtile * 128 + rowblk * 32 + rl;
            runmax[q] = -3.4e38f;
            delta[q] = __fmaf_rn(0.025f * sqrtf(g_rn[grow[q]]), sw, 4e-3f);
        }
    }

    // ldmatrix lane address components (constant per lane across tiles)
    // A: m = rowblk*32 + mb*16 + (lane&15), col16 = (lane>>4)*16
    const int am = rowblk * 32 + (lane & 15);
    const uint32_t acol = (uint32_t)((lane >> 4) * 16);
    // B: n = cg*32 + nbp*16 + ((lane>>4)&1)*8 + (lane&7), col16 = ((lane>>3)&1)*16
    const int bn = cg * 32 + ((lane >> 4) & 1) * 8 + (lane & 7);
    const uint32_t bcol = (uint32_t)(((lane >> 3) & 1) * 16);

    const __nv_bfloat16* __restrict__ wb = g_wbf + (size_t)head * KK * DD;
    const float* __restrict__ wnb = g_wn + head * KK;
    const int csplit0 = split * (KK / NCSPLIT);

    for (int tile = 0; tile < NTILES; tile++) {
        const int c0 = csplit0 + tile * TILEN;
        __syncthreads();   // A staged (1st iter) / prev tile's mma done

        // ---- stage B tile ----
        {
            const int code = tid >> 2, q = tid & 3;
            const uint4* src = (const uint4*)(wb
                + (size_t)(c0 + code) * DD + q * 32);
            char* dstb = (char*)Bs + (q >> 1) * 8192;
#pragma unroll
            for (int i = 0; i < 4; i++) {
                uint32_t x = (uint32_t)(code * 128 + (q & 1) * 64 + i * 16);
                *(uint4*)(dstb + SW128(x)) = src[i];
            }
        }
        __syncthreads();

        float acc[2][4][4];
#pragma unroll
        for (int mb = 0; mb < 2; mb++)
#pragma unroll
            for (int nb = 0; nb < 4; nb++)
#pragma unroll
                for (int r = 0; r < 4; r++) acc[mb][nb][r] = 0.0f;

#pragma unroll
        for (int s = 0; s < 8; s++) {
            const uint32_t kblk = (uint32_t)(s >> 2);
            const uint32_t kcol = (uint32_t)((s & 3) * 32);

            uint32_t af[2][4];
#pragma unroll
            for (int mb = 0; mb < 2; mb++) {
                int m = am + mb * 16;
                uint32_t x = (uint32_t)(m * 128) + kcol + acol;
                uint32_t a = saddrA + kblk * 16384 + SW128(x);
                LDMX4(af[mb][0], af[mb][1], af[mb][2], af[mb][3], a);
            }
            uint32_t bf[8];
#pragma unroll
            for (int nbp = 0; nbp < 2; nbp++) {
                int n = bn + nbp * 16;
                uint32_t x = (uint32_t)(n * 128) + kcol + bcol;
                uint32_t a = saddrB + kblk * 8192 + SW128(x);
                LDMX4(bf[nbp * 4 + 0], bf[nbp * 4 + 1],
                      bf[nbp * 4 + 2], bf[nbp * 4 + 3], a);
            }
#pragma unroll
            for (int mb = 0; mb < 2; mb++) {
#pragma unroll
                for (int nb = 0; nb < 4; nb++)
                    MMA16816(acc[mb][nb], af[mb],
                             bf[nb * 2], bf[nb * 2 + 1]);
            }
        }

        // ---- epilogue: threshold + candidate append (regs + gmem only) ----
#pragma unroll
        for (int mb = 0; mb < 2; mb++) {
#pragma unroll
            for (int nb = 0; nb < 4; nb++) {
#pragma unroll
                for (int r = 0; r < 4; r++) {
                    const int q = mb * 2 + (r >> 1);        // lane-row slot
                    const int code = c0 + cg * 32 + nb * 8 + 2 * tig + (r & 1);
                    float sbv = __fmaf_rn(2.0f, acc[mb][nb][r],
                                          -__ldg(&wnb[code]));
                    if (sbv >= runmax[q] - delta[q]) {
                        int p = atomicAdd(&g_ccnt[grow[q]], 1);
                        if (p < CAP) g_cand[grow[q] * CAP + p] = code;
                    }
                    if (sbv > runmax[q]) runmax[q] = sbv;
                }
            }
        }
    }
}

// ---- exact rescore of candidates (bit-exact reference formula) ----
__global__ void __launch_bounds__(256) rescore_k(const float* __restrict__ emb,
                                                 int head) {
    __shared__ float rs[8][DD];
    const int wid = threadIdx.x >> 5, lane = threadIdx.x & 31;
    const int row = blockIdx.x * 8 + wid;

    ((float4*)rs[wid])[lane] = ((const float4*)(g_resid + (size_t)row * DD))[lane];
    __syncwarp();

    const float rn = g_rn[row];
    int cnt = g_ccnt[row];
    if (cnt > CAP) cnt = CAP;
    const float* __restrict__ Wb = emb + (size_t)head * KK * DD;
    const float* __restrict__ wnb = g_wn + head * KK;
    const float* __restrict__ r = rs[wid];

    float bsv = -3.4e38f;
    int bidx = 0x7fffffff;
    for (int ci = lane; ci < cnt; ci += 32) {
        int code = g_cand[row * CAP + ci];
        const float4* wp = (const float4*)(Wb + (size_t)code * DD);
        float acc = 0.0f;
#pragma unroll
        for (int i = 0; i < 32; i++) {       // sequential chain, k ascending
            float4 w = __ldg(&wp[i]);
            acc = __fmaf_rn(r[4 * i + 0], w.x, acc);
            acc = __fmaf_rn(r[4 * i + 1], w.y, acc);
            acc = __fmaf_rn(r[4 * i + 2], w.z, acc);
            acc = __fmaf_rn(r[4 * i + 3], w.w, acc);
        }
        float t1 = __fadd_rn(rn, wnb[code]);
        float s = -__fsub_rn(t1, __fmul_rn(2.0f, acc));
        if (s > bsv || (s == bsv && code < bidx)) { bsv = s; bidx = code; }
    }
#pragma unroll
    for (int off = 16; off; off >>= 1) {
        float os = __shfl_xor_sync(0xffffffffu, bsv, off);
        int   oi = __shfl_xor_sync(0xffffffffu, bidx, off);
        if (os > bsv || (os == bsv && oi < bidx)) { bsv = os; bidx = oi; }
    }
    if (lane == 0) g_sel[row] = (bidx == 0x7fffffff) ? 0 : bidx;
}

__global__ void update_k(const float* __restrict__ emb, int head) {
    const int b = blockIdx.x, d = threadIdx.x;
    const int idx = g_sel[b];
    const float w = emb[(size_t)head * KK * DD + (size_t)idx * DD + d];
    g_resid[b * DD + d] -= w;
    g_quant[b * DD + d] += w;
    if (d == 0) g_codes[b * HH + head] = idx;
}

__global__ void write_k(float* __restrict__ out,
                        int loss_off, int quant_off, int codes_off) {
    int i = blockIdx.x * blockDim.x + threadIdx.x;
    if (loss_off >= 0 && i < BB) out[loss_off + i] = 0.0f;
    if (quant_off >= 0 && i < BB * DD) out[quant_off + i] = g_quant[i];
    if (codes_off >= 0 && i < BB * HH) out[codes_off + i] = (float)g_codes[i];
}

extern "C" void kernel_launch(void* const* d_in, const int* in_sizes, int n_in,
                              void* d_out, int out_size) {
    const float* inputs = nullptr;
    const float* emb = nullptr;
    for (int i = 0; i < n_in; i++) {
        if (in_sizes[i] == BB * DD) inputs = (const float*)d_in[i];
        else if (in_sizes[i] == HH * KK * DD) emb = (const float*)d_in[i];
    }
    if (!inputs || !emb) { inputs = (const float*)d_in[0]; emb = (const float*)d_in[1]; }

    init_k<<<(BB * DD + 255) / 256, 256>>>(inputs);
    wn_k<<<(HH * KK) / 8, 256>>>(emb);
    wconv_k<<<(HH * KK * DD + 255) / 256, 256>>>(emb);

    for (int h = 0; h < HH; h++) {
        rn_k<<<BB / 8, 256>>>();
        bconv_k<<<(BB * DD + 255) / 256, 256>>>();
        dim3 grid(ROWTILES, NCSPLIT);
        mma_score_k<<<grid, 256>>>(h);
        rescore_k<<<BB / 8, 256>>>(emb, h);
        update_k<<<BB, DD>>>(emb, h);
    }

    int loss_off = -1, quant_off = -1, codes_off = -1;
    if (out_size == BB + BB * DD + BB * HH) {
        loss_off = 0; quant_off = BB; codes_off = BB + BB * DD;
    } else if (out_size == BB * DD) {
        quant_off = 0;
    } else if (out_size == BB * DD + BB * HH) {
        quant_off = 0; codes_off = BB * DD;
    } else if (out_size == BB + BB * DD) {
        loss_off = 0; quant_off = BB;
    } else {
        quant_off = 0;
    }
    write_k<<<(BB * DD + 255) / 256, 256>>>((float*)d_out,
                                            loss_off, quant_off, codes_off);
}

// round 13
// speedup vs baseline: 4.7149x; 1.8288x over previous
#include <cuda_runtime.h>
#include <cuda_bf16.h>
#include <cstddef>
#include <cstdint>

#define BB 4096
#define DD 128
#define KK 32768
#define HH 3
#define CAP 1024
#define NCSPLIT 8
#define TILEN 64
#define NTILES (KK / NCSPLIT / TILEN)   // 64 tiles per CTA
#define ROWTILES (BB / 128)             // 32

// ---- device scratch (no allocation allowed) ----
__device__ float g_resid[BB * DD];
__device__ float g_quant[BB * DD];
__device__ float g_rn[BB];
__device__ float g_wn[HH * KK];
__device__ int   g_wnmaxbits[HH];
__device__ __nv_bfloat16 g_rbf[BB * DD];
__device__ __nv_bfloat16 g_wbf[HH * KK * DD];
__device__ int   g_ccnt[BB];
__device__ int   g_cand[BB * CAP];
__device__ int   g_sel[BB];
__device__ int   g_codes[BB * HH];

#define SW128(x) ((x) ^ (((x) >> 3) & 0x70))

__device__ __forceinline__ uint32_t smem_u32(const void* p) {
    uint32_t a;
    asm("{ .reg .u64 t; cvta.to.shared.u64 t, %1; cvt.u32.u64 %0, t; }"
        : "=r"(a) : "l"(p));
    return a;
}

#define LDMX4(r0, r1, r2, r3, a) \
    asm volatile("ldmatrix.sync.aligned.m8n8.x4.shared.b16 {%0,%1,%2,%3}, [%4];" \
                 : "=r"(r0), "=r"(r1), "=r"(r2), "=r"(r3) : "r"(a))

#define MMA16816(c, av, b0, b1) \
    asm volatile("mma.sync.aligned.m16n8k16.row.col.f32.bf16.bf16.f32 " \
                 "{%0,%1,%2,%3}, {%4,%5,%6,%7}, {%8,%9}, {%0,%1,%2,%3};" \
                 : "+f"((c)[0]), "+f"((c)[1]), "+f"((c)[2]), "+f"((c)[3]) \
                 : "r"((av)[0]), "r"((av)[1]), "r"((av)[2]), "r"((av)[3]), \
                   "r"(b0), "r"(b1))

// ---- small kernels ----
__global__ void init_k(const float* __restrict__ in) {
    int i = blockIdx.x * blockDim.x + threadIdx.x;
    if (i < BB * DD) { g_resid[i] = in[i]; g_quant[i] = 0.0f; }
    if (i < HH) g_wnmaxbits[i] = 0;
}

__device__ __forceinline__ float row_sumsq_xla(const float* __restrict__ base,
                                               int lane) {
    float a =        __fmul_rn(base[lane],      base[lane]);
    a = __fadd_rn(a, __fmul_rn(base[lane + 32], base[lane + 32]));
    a = __fadd_rn(a, __fmul_rn(base[lane + 64], base[lane + 64]));
    a = __fadd_rn(a, __fmul_rn(base[lane + 96], base[lane + 96]));
#pragma unroll
    for (int off = 16; off; off >>= 1)
        a = __fadd_rn(a, __shfl_down_sync(0xffffffffu, a, off));
    return a;
}

__global__ void wn_k(const float* __restrict__ emb) {
    const int warp = threadIdx.x >> 5, lane = threadIdx.x & 31;
    const int code = blockIdx.x * 8 + warp;
    if (code >= HH * KK) return;
    float a = row_sumsq_xla(emb + (size_t)code * DD, lane);
    if (lane == 0) {
        g_wn[code] = a;
        atomicMax(&g_wnmaxbits[code >> 15], __float_as_int(a));
    }
}

__global__ void wconv_k(const float* __restrict__ emb) {
    int i = blockIdx.x * blockDim.x + threadIdx.x;
    if (i < HH * KK * DD) g_wbf[i] = __float2bfloat16_rn(emb[i]);
}

// Fused per-head prep: rn (XLA-pattern sum of squares), bf16 convert of the
// residual, candidate-count reset. One warp per row.
__global__ void prep_k() {
    const int wid = threadIdx.x >> 5, lane = threadIdx.x & 31;
    const int row = blockIdx.x * 8 + wid;
    const float* __restrict__ base = g_resid + (size_t)row * DD;

    float v0 = base[lane], v1 = base[lane + 32];
    float v2 = base[lane + 64], v3 = base[lane + 96];

    float a =        __fmul_rn(v0, v0);
    a = __fadd_rn(a, __fmul_rn(v1, v1));
    a = __fadd_rn(a, __fmul_rn(v2, v2));
    a = __fadd_rn(a, __fmul_rn(v3, v3));
#pragma unroll
    for (int off = 16; off; off >>= 1)
        a = __fadd_rn(a, __shfl_down_sync(0xffffffffu, a, off));

    __nv_bfloat16* rb = g_rbf + (size_t)row * DD;
    rb[lane]      = __float2bfloat16_rn(v0);
    rb[lane + 32] = __float2bfloat16_rn(v1);
    rb[lane + 64] = __float2bfloat16_rn(v2);
    rb[lane + 96] = __float2bfloat16_rn(v3);

    if (lane == 0) { g_rn[row] = a; g_ccnt[row] = 0; }
}

// ---- mma.sync bf16 approximate scorer + candidate collection ----
// CTA: 128 rows x 64-code tiles over KK/NCSPLIT codes. 8 warps; warp tile =
// 32 rows (2 m16 blocks) x 32 codes (4 n8 blocks); K=128 in 8 k16 steps.
// A smem: [2 kblk][128 rows][64 bf16] SW128 (32KB, staged once).
// B smem: [2 kblk][64 codes][64 bf16] SW128 (16KB, register-prefetch
// pipelined: LDG for tile t+1 issues before the MMA loop of tile t).
// 2 CTAs/SM (launch_bounds), all 256 CTAs resident in one wave.
// Candidate rule: keep code if 2*d - wn >= runmax - delta, delta >= 2x the
// bf16 conversion error bound -> true argmax provably retained. runmax is
// shared across the 4 tig-lanes of each row every tile (only tightens).
__global__ void __launch_bounds__(256, 2) mma_score_k(int head) {
    __shared__ __nv_bfloat16 As[2 * 128 * 64];   // 32KB
    __shared__ __nv_bfloat16 Bs[2 * 64 * 64];    // 16KB

    const uint32_t saddrA = smem_u32(As);
    const uint32_t saddrB = smem_u32(Bs);
    const int tid  = threadIdx.x;
    const int wid  = tid >> 5;
    const int lane = tid & 31;
    const int rowblk = wid & 3;        // 32-row group
    const int cg     = wid >> 2;       // 32-code group (0..1)
    const int rowtile = blockIdx.x;
    const int split   = blockIdx.y;

    // ---- stage A once ----
    {
        const int row = tid >> 1, half = tid & 1;
        const uint4* src = (const uint4*)(g_rbf
            + (size_t)(rowtile * 128 + row) * DD + half * 64);
        char* dstb = (char*)As + half * 16384;
#pragma unroll
        for (int i = 0; i < 8; i++) {
            uint32_t x = (uint32_t)(row * 128 + i * 16);
            *(uint4*)(dstb + SW128(x)) = src[i];
        }
    }

    // Per-lane rows: mb in {0,1} x rowpart in {0,8}: 4 rows.
    const int gid = lane >> 2, tig = lane & 3;
    int   grow[4];
    float runmax[4], delta[4];
    {
        float wmax = __int_as_float(g_wnmaxbits[head]);
        float sw = sqrtf(wmax);
#pragma unroll
        for (int q = 0; q < 4; q++) {
            int rl = (q >> 1) * 16 + gid + (q & 1) * 8;
            grow[q] = rowtile * 128 + rowblk * 32 + rl;
            runmax[q] = -3.4e38f;
            delta[q] = __fmaf_rn(0.025f * sqrtf(g_rn[grow[q]]), sw, 4e-3f);
        }
    }

    // ldmatrix lane address components (constant per lane across tiles)
    const int am = rowblk * 32 + (lane & 15);
    const uint32_t acol = (uint32_t)((lane >> 4) * 16);
    const int bn = cg * 32 + ((lane >> 4) & 1) * 8 + (lane & 7);
    const uint32_t bcol = (uint32_t)(((lane >> 3) & 1) * 16);

    const __nv_bfloat16* __restrict__ wb = g_wbf + (size_t)head * KK * DD;
    const float* __restrict__ wnb = g_wn + head * KK;
    const int csplit0 = split * (KK / NCSPLIT);

    // B staging geometry for this thread
    const int scode = tid >> 2, sq = tid & 3;
    char* const sdstb = (char*)Bs + (sq >> 1) * 8192;

    // ---- stage B tile 0 ----
    {
        const uint4* src = (const uint4*)(wb
            + (size_t)(csplit0 + scode) * DD + sq * 32);
#pragma unroll
        for (int i = 0; i < 4; i++) {
            uint32_t x = (uint32_t)(scode * 128 + (sq & 1) * 64 + i * 16);
            *(uint4*)(sdstb + SW128(x)) = src[i];
        }
    }
    __syncthreads();   // A and B0 staged

    for (int tile = 0; tile < NTILES; tile++) {
        const int c0 = csplit0 + tile * TILEN;

        // Prefetch next tile's B into registers (LDG overlaps the MMA loop)
        uint4 pre[4];
        if (tile + 1 < NTILES) {
            const uint4* src = (const uint4*)(wb
                + (size_t)(c0 + TILEN + scode) * DD + sq * 32);
#pragma unroll
            for (int i = 0; i < 4; i++) pre[i] = src[i];
        }

        float acc[2][4][4];
#pragma unroll
        for (int mb = 0; mb < 2; mb++)
#pragma unroll
            for (int nb = 0; nb < 4; nb++)
#pragma unroll
                for (int r = 0; r < 4; r++) acc[mb][nb][r] = 0.0f;

#pragma unroll
        for (int s = 0; s < 8; s++) {
            const uint32_t kblk = (uint32_t)(s >> 2);
            const uint32_t kcol = (uint32_t)((s & 3) * 32);

            uint32_t af[2][4];
#pragma unroll
            for (int mb = 0; mb < 2; mb++) {
                int m = am + mb * 16;
                uint32_t x = (uint32_t)(m * 128) + kcol + acol;
                uint32_t a = saddrA + kblk * 16384 + SW128(x);
                LDMX4(af[mb][0], af[mb][1], af[mb][2], af[mb][3], a);
            }
            uint32_t bf[8];
#pragma unroll
            for (int nbp = 0; nbp < 2; nbp++) {
                int n = bn + nbp * 16;
                uint32_t x = (uint32_t)(n * 128) + kcol + bcol;
                uint32_t a = saddrB + kblk * 8192 + SW128(x);
                LDMX4(bf[nbp * 4 + 0], bf[nbp * 4 + 1],
                      bf[nbp * 4 + 2], bf[nbp * 4 + 3], a);
            }
#pragma unroll
            for (int mb = 0; mb < 2; mb++) {
#pragma unroll
                for (int nb = 0; nb < 4; nb++)
                    MMA16816(acc[mb][nb], af[mb],
                             bf[nb * 2], bf[nb * 2 + 1]);
            }
        }

        // ---- epilogue: threshold + candidate append ----
#pragma unroll
        for (int mb = 0; mb < 2; mb++) {
#pragma unroll
            for (int nb = 0; nb < 4; nb++) {
#pragma unroll
                for (int r = 0; r < 4; r++) {
                    const int q = mb * 2 + (r >> 1);
                    const int code = c0 + cg * 32 + nb * 8 + 2 * tig + (r & 1);
                    float sbv = __fmaf_rn(2.0f, acc[mb][nb][r],
                                          -__ldg(&wnb[code]));
                    if (sbv >= runmax[q] - delta[q]) {
                        int p = atomicAdd(&g_ccnt[grow[q]], 1);
                        if (p < CAP) g_cand[grow[q] * CAP + p] = code;
                    }
                    if (sbv > runmax[q]) runmax[q] = sbv;
                }
            }
        }
        // Share runmax across the 4 tig-lanes of each row (tightens filter)
#pragma unroll
        for (int q = 0; q < 4; q++) {
            float m1 = __shfl_xor_sync(0xffffffffu, runmax[q], 1);
            runmax[q] = fmaxf(runmax[q], m1);
            float m2 = __shfl_xor_sync(0xffffffffu, runmax[q], 2);
            runmax[q] = fmaxf(runmax[q], m2);
        }

        __syncthreads();   // all warps done reading Bs
        if (tile + 1 < NTILES) {
#pragma unroll
            for (int i = 0; i < 4; i++) {
                uint32_t x = (uint32_t)(scode * 128 + (sq & 1) * 64 + i * 16);
                *(uint4*)(sdstb + SW128(x)) = pre[i];
            }
        }
        __syncthreads();   // Bs refilled
    }
}

// ---- exact rescore of candidates (bit-exact reference formula) ----
__global__ void __launch_bounds__(256) rescore_k(const float* __restrict__ emb,
                                                 int head) {
    __shared__ float rs[8][DD];
    const int wid = threadIdx.x >> 5, lane = threadIdx.x & 31;
    const int row = blockIdx.x * 8 + wid;

    ((float4*)rs[wid])[lane] = ((const float4*)(g_resid + (size_t)row * DD))[lane];
    __syncwarp();

    const float rn = g_rn[row];
    int cnt = g_ccnt[row];
    if (cnt > CAP) cnt = CAP;
    const float* __restrict__ Wb = emb + (size_t)head * KK * DD;
    const float* __restrict__ wnb = g_wn + head * KK;
    const float* __restrict__ r = rs[wid];

    float bsv = -3.4e38f;
    int bidx = 0x7fffffff;
    for (int ci = lane; ci < cnt; ci += 32) {
        int code = g_cand[row * CAP + ci];
        const float4* wp = (const float4*)(Wb + (size_t)code * DD);
        float acc = 0.0f;
#pragma unroll
        for (int i = 0; i < 32; i++) {       // sequential chain, k ascending
            float4 w = __ldg(&wp[i]);
            acc = __fmaf_rn(r[4 * i + 0], w.x, acc);
            acc = __fmaf_rn(r[4 * i + 1], w.y, acc);
            acc = __fmaf_rn(r[4 * i + 2], w.z, acc);
            acc = __fmaf_rn(r[4 * i + 3], w.w, acc);
        }
        float t1 = __fadd_rn(rn, wnb[code]);
        float s = -__fsub_rn(t1, __fmul_rn(2.0f, acc));
        if (s > bsv || (s == bsv && code < bidx)) { bsv = s; bidx = code; }
    }
#pragma unroll
    for (int off = 16; off; off >>= 1) {
        float os = __shfl_xor_sync(0xffffffffu, bsv, off);
        int   oi = __shfl_xor_sync(0xffffffffu, bidx, off);
        if (os > bsv || (os == bsv && oi < bidx)) { bsv = os; bidx = oi; }
    }
    if (lane == 0) g_sel[row] = (bidx == 0x7fffffff) ? 0 : bidx;
}

__global__ void update_k(const float* __restrict__ emb, int head) {
    const int b = blockIdx.x, d = threadIdx.x;
    const int idx = g_sel[b];
    const float w = emb[(size_t)head * KK * DD + (size_t)idx * DD + d];
    g_resid[b * DD + d] -= w;
    g_quant[b * DD + d] += w;
    if (d == 0) g_codes[b * HH + head] = idx;
}

__global__ void write_k(float* __restrict__ out,
                        int loss_off, int quant_off, int codes_off) {
    int i = blockIdx.x * blockDim.x + threadIdx.x;
    if (loss_off >= 0 && i < BB) out[loss_off + i] = 0.0f;
    if (quant_off >= 0 && i < BB * DD) out[quant_off + i] = g_quant[i];
    if (codes_off >= 0 && i < BB * HH) out[codes_off + i] = (float)g_codes[i];
}

extern "C" void kernel_launch(void* const* d_in, const int* in_sizes, int n_in,
                              void* d_out, int out_size) {
    const float* inputs = nullptr;
    const float* emb = nullptr;
    for (int i = 0; i < n_in; i++) {
        if (in_sizes[i] == BB * DD) inputs = (const float*)d_in[i];
        else if (in_sizes[i] == HH * KK * DD) emb = (const float*)d_in[i];
    }
    if (!inputs || !emb) { inputs = (const float*)d_in[0]; emb = (const float*)d_in[1]; }

    init_k<<<(BB * DD + 255) / 256, 256>>>(inputs);
    wn_k<<<(HH * KK) / 8, 256>>>(emb);
    wconv_k<<<(HH * KK * DD + 255) / 256, 256>>>(emb);

    for (int h = 0; h < HH; h++) {
        prep_k<<<BB / 8, 256>>>();
        dim3 grid(ROWTILES, NCSPLIT);
        mma_score_k<<<grid, 256>>>(h);
        rescore_k<<<BB / 8, 256>>>(emb, h);
        update_k<<<BB, DD>>>(emb, h);
    }

    int loss_off = -1, quant_off = -1, codes_off = -1;
    if (out_size == BB + BB * DD + BB * HH) {
        loss_off = 0; quant_off = BB; codes_off = BB + BB * DD;
    } else if (out_size == BB * DD) {
        quant_off = 0;
    } else if (out_size == BB * DD + BB * HH) {
        quant_off = 0; codes_off = BB * DD;
    } else if (out_size == BB + BB * DD) {
        loss_off = 0; quant_off = BB;
    } else {
        quant_off = 0;
    }
    write_k<<<(BB * DD + 255) / 256, 256>>>((float*)d_out,
                                            loss_off, quant_off, codes_off);
}

// round 16
// speedup vs baseline: 7.3317x; 1.5550x over previous
#include <cuda_runtime.h>
#include <cuda_bf16.h>
#include <cstddef>
#include <cstdint>

#define BB 4096
#define DD 128
#define KK 32768
#define HH 3
#define CAP 1024
#define NCSPLIT 8
#define TILEN 64
#define NTILES (KK / NCSPLIT / TILEN)   // 64 tiles per CTA
#define ROWTILES (BB / 128)             // 32

// ---- device scratch (no allocation allowed) ----
__device__ float g_resid[BB * DD];
__device__ float g_quant[BB * DD];
__device__ float g_rn[BB];
__device__ float g_wn[HH * KK];
__device__ int   g_wnmaxbits[HH];
__device__ __nv_bfloat16 g_rbf[BB * DD];
__device__ __nv_bfloat16 g_wbf[HH * KK * DD];
__device__ int      g_ccnt[BB];
__device__ unsigned g_rowmax[BB];        // order-preserving-encoded approx max
__device__ int   g_cand[BB * CAP];
__device__ int   g_sel[BB];
__device__ int   g_codes[BB * HH];

#define SW128(x) ((x) ^ (((x) >> 3) & 0x70))
#define ENC_MIN 0x00800000u              // enc_f(-3.4e38f)

__device__ __forceinline__ unsigned enc_f(float f) {
    unsigned u = __float_as_uint(f);
    return (u & 0x80000000u) ? ~u : (u | 0x80000000u);
}
__device__ __forceinline__ float dec_f(unsigned k) {
    return (k & 0x80000000u) ? __uint_as_float(k ^ 0x80000000u)
                             : __uint_as_float(~k);
}

__device__ __forceinline__ uint32_t smem_u32(const void* p) {
    uint32_t a;
    asm("{ .reg .u64 t; cvta.to.shared.u64 t, %1; cvt.u32.u64 %0, t; }"
        : "=r"(a) : "l"(p));
    return a;
}

#define LDMX4(r0, r1, r2, r3, a) \
    asm volatile("ldmatrix.sync.aligned.m8n8.x4.shared.b16 {%0,%1,%2,%3}, [%4];" \
                 : "=r"(r0), "=r"(r1), "=r"(r2), "=r"(r3) : "r"(a))

#define MMA16816(c, av, b0, b1) \
    asm volatile("mma.sync.aligned.m16n8k16.row.col.f32.bf16.bf16.f32 " \
                 "{%0,%1,%2,%3}, {%4,%5,%6,%7}, {%8,%9}, {%0,%1,%2,%3};" \
                 : "+f"((c)[0]), "+f"((c)[1]), "+f"((c)[2]), "+f"((c)[3]) \
                 : "r"((av)[0]), "r"((av)[1]), "r"((av)[2]), "r"((av)[3]), \
                   "r"(b0), "r"(b1))

// ---- small kernels ----
__global__ void init_k(const float* __restrict__ in) {
    int i = blockIdx.x * blockDim.x + threadIdx.x;
    if (i < BB * DD) { g_resid[i] = in[i]; g_quant[i] = 0.0f; }
    if (i < HH) g_wnmaxbits[i] = 0;
}

__device__ __forceinline__ float row_sumsq_xla(const float* __restrict__ base,
                                               int lane) {
    float a =        __fmul_rn(base[lane],      base[lane]);
    a = __fadd_rn(a, __fmul_rn(base[lane + 32], base[lane + 32]));
    a = __fadd_rn(a, __fmul_rn(base[lane + 64], base[lane + 64]));
    a = __fadd_rn(a, __fmul_rn(base[lane + 96], base[lane + 96]));
#pragma unroll
    for (int off = 16; off; off >>= 1)
        a = __fadd_rn(a, __shfl_down_sync(0xffffffffu, a, off));
    return a;
}

__global__ void wn_k(const float* __restrict__ emb) {
    const int warp = threadIdx.x >> 5, lane = threadIdx.x & 31;
    const int code = blockIdx.x * 8 + warp;
    if (code >= HH * KK) return;
    float a = row_sumsq_xla(emb + (size_t)code * DD, lane);
    if (lane == 0) {
        g_wn[code] = a;
        atomicMax(&g_wnmaxbits[code >> 15], __float_as_int(a));
    }
}

__global__ void wconv_k(const float* __restrict__ emb) {
    int i = blockIdx.x * blockDim.x + threadIdx.x;
    if (i < HH * KK * DD) g_wbf[i] = __float2bfloat16_rn(emb[i]);
}

// Fused per-head prep: rn, bf16 residual convert, candidate/rowmax reset.
__global__ void prep_k() {
    const int wid = threadIdx.x >> 5, lane = threadIdx.x & 31;
    const int row = blockIdx.x * 8 + wid;
    const float* __restrict__ base = g_resid + (size_t)row * DD;

    float v0 = base[lane], v1 = base[lane + 32];
    float v2 = base[lane + 64], v3 = base[lane + 96];

    float a =        __fmul_rn(v0, v0);
    a = __fadd_rn(a, __fmul_rn(v1, v1));
    a = __fadd_rn(a, __fmul_rn(v2, v2));
    a = __fadd_rn(a, __fmul_rn(v3, v3));
#pragma unroll
    for (int off = 16; off; off >>= 1)
        a = __fadd_rn(a, __shfl_down_sync(0xffffffffu, a, off));

    __nv_bfloat16* rb = g_rbf + (size_t)row * DD;
    rb[lane]      = __float2bfloat16_rn(v0);
    rb[lane + 32] = __float2bfloat16_rn(v1);
    rb[lane + 64] = __float2bfloat16_rn(v2);
    rb[lane + 96] = __float2bfloat16_rn(v3);

    if (lane == 0) { g_rn[row] = a; g_ccnt[row] = 0; g_rowmax[row] = ENC_MIN; }
}

// ---- mma.sync bf16 approximate scorer + candidate collection ----
// Epilogue order per tile: (1) score, (2) fold tile max into runmax (incl.
// cross-CTA g_rowmax via one atomicMax per row-slot), (3) THEN threshold.
// Threshold M - delta with M = any max of real approx scores of the row is
// provably retention-safe for the exact argmax (delta >= 2x bf16 conv bound).
__global__ void __launch_bounds__(256, 2) mma_score_k(int head) {
    __shared__ __nv_bfloat16 As[2 * 128 * 64];   // 32KB
    __shared__ __nv_bfloat16 Bs[2 * 64 * 64];    // 16KB

    const uint32_t saddrA = smem_u32(As);
    const uint32_t saddrB = smem_u32(Bs);
    const int tid  = threadIdx.x;
    const int wid  = tid >> 5;
    const int lane = tid & 31;
    const int rowblk = wid & 3;
    const int cg     = wid >> 2;
    const int rowtile = blockIdx.x;
    const int split   = blockIdx.y;

    // ---- stage A once ----
    {
        const int row = tid >> 1, half = tid & 1;
        const uint4* src = (const uint4*)(g_rbf
            + (size_t)(rowtile * 128 + row) * DD + half * 64);
        char* dstb = (char*)As + half * 16384;
#pragma unroll
        for (int i = 0; i < 8; i++) {
            uint32_t x = (uint32_t)(row * 128 + i * 16);
            *(uint4*)(dstb + SW128(x)) = src[i];
        }
    }

    const int gid = lane >> 2, tig = lane & 3;
    int   grow[4];
    float runmax[4], delta[4];
    {
        float wmax = __int_as_float(g_wnmaxbits[head]);
        float sw = sqrtf(wmax);
#pragma unroll
        for (int q = 0; q < 4; q++) {
            int rl = (q >> 1) * 16 + gid + (q & 1) * 8;
            grow[q] = rowtile * 128 + rowblk * 32 + rl;
            runmax[q] = -3.4e38f;
            delta[q] = __fmaf_rn(0.025f * sqrtf(g_rn[grow[q]]), sw, 4e-3f);
        }
    }

    const int am = rowblk * 32 + (lane & 15);
    const uint32_t acol = (uint32_t)((lane >> 4) * 16);
    const int bn = cg * 32 + ((lane >> 4) & 1) * 8 + (lane & 7);
    const uint32_t bcol = (uint32_t)(((lane >> 3) & 1) * 16);

    const __nv_bfloat16* __restrict__ wb = g_wbf + (size_t)head * KK * DD;
    const float* __restrict__ wnb = g_wn + head * KK;
    const int csplit0 = split * (KK / NCSPLIT);

    const int scode = tid >> 2, sq = tid & 3;
    char* const sdstb = (char*)Bs + (sq >> 1) * 8192;

    // ---- stage B tile 0 ----
    {
        const uint4* src = (const uint4*)(wb
            + (size_t)(csplit0 + scode) * DD + sq * 32);
#pragma unroll
        for (int i = 0; i < 4; i++) {
            uint32_t x = (uint32_t)(scode * 128 + (sq & 1) * 64 + i * 16);
            *(uint4*)(sdstb + SW128(x)) = src[i];
        }
    }
    __syncthreads();

    for (int tile = 0; tile < NTILES; tile++) {
        const int c0 = csplit0 + tile * TILEN;

        // Prefetch next tile's B into registers (overlaps the MMA loop)
        uint4 pre[4];
        if (tile + 1 < NTILES) {
            const uint4* src = (const uint4*)(wb
                + (size_t)(c0 + TILEN + scode) * DD + sq * 32);
#pragma unroll
            for (int i = 0; i < 4; i++) pre[i] = src[i];
        }

        float acc[2][4][4];
#pragma unroll
        for (int mb = 0; mb < 2; mb++)
#pragma unroll
            for (int nb = 0; nb < 4; nb++)
#pragma unroll
                for (int r = 0; r < 4; r++) acc[mb][nb][r] = 0.0f;

#pragma unroll
        for (int s = 0; s < 8; s++) {
            const uint32_t kblk = (uint32_t)(s >> 2);
            const uint32_t kcol = (uint32_t)((s & 3) * 32);

            uint32_t af[2][4];
#pragma unroll
            for (int mb = 0; mb < 2; mb++) {
                int m = am + mb * 16;
                uint32_t x = (uint32_t)(m * 128) + kcol + acol;
                uint32_t a = saddrA + kblk * 16384 + SW128(x);
                LDMX4(af[mb][0], af[mb][1], af[mb][2], af[mb][3], a);
            }
            uint32_t bf[8];
#pragma unroll
            for (int nbp = 0; nbp < 2; nbp++) {
                int n = bn + nbp * 16;
                uint32_t x = (uint32_t)(n * 128) + kcol + bcol;
                uint32_t a = saddrB + kblk * 8192 + SW128(x);
                LDMX4(bf[nbp * 4 + 0], bf[nbp * 4 + 1],
                      bf[nbp * 4 + 2], bf[nbp * 4 + 3], a);
            }
#pragma unroll
            for (int mb = 0; mb < 2; mb++) {
#pragma unroll
                for (int nb = 0; nb < 4; nb++)
                    MMA16816(acc[mb][nb], af[mb],
                             bf[nb * 2], bf[nb * 2 + 1]);
            }
        }

        // ---- epilogue ----
        // (1) scores in place: acc := 2*d - wn
        float2 wn2[4];
#pragma unroll
        for (int nb = 0; nb < 4; nb++)
            wn2[nb] = __ldg((const float2*)&wnb[c0 + cg * 32 + nb * 8 + 2 * tig]);
#pragma unroll
        for (int mb = 0; mb < 2; mb++)
#pragma unroll
            for (int nb = 0; nb < 4; nb++)
#pragma unroll
                for (int r = 0; r < 4; r++)
                    acc[mb][nb][r] = __fmaf_rn(2.0f, acc[mb][nb][r],
                                               -((r & 1) ? wn2[nb].y : wn2[nb].x));

        // (2) fold tile max into runmax; share across tig lanes + all CTAs
#pragma unroll
        for (int q = 0; q < 4; q++) {
            const int mb = q >> 1, rb2 = (q & 1) * 2;
            float m = runmax[q];
#pragma unroll
            for (int nb = 0; nb < 4; nb++) {
                m = fmaxf(m, acc[mb][nb][rb2]);
                m = fmaxf(m, acc[mb][nb][rb2 + 1]);
            }
            m = fmaxf(m, __shfl_xor_sync(0xffffffffu, m, 1));
            m = fmaxf(m, __shfl_xor_sync(0xffffffffu, m, 2));
            if (tig == 0) {
                unsigned old = atomicMax(&g_rowmax[grow[q]], enc_f(m));
                m = fmaxf(m, dec_f(old));
            }
            m = __shfl_sync(0xffffffffu, m, lane & ~3);
            runmax[q] = m;
        }

        // (3) threshold & append
#pragma unroll
        for (int mb = 0; mb < 2; mb++) {
#pragma unroll
            for (int nb = 0; nb < 4; nb++) {
#pragma unroll
                for (int r = 0; r < 4; r++) {
                    const int q = mb * 2 + (r >> 1);
                    if (acc[mb][nb][r] >= runmax[q] - delta[q]) {
                        const int code = c0 + cg * 32 + nb * 8 + 2 * tig + (r & 1);
                        int p = atomicAdd(&g_ccnt[grow[q]], 1);
                        if (p < CAP) g_cand[grow[q] * CAP + p] = code;
                    }
                }
            }
        }

        __syncthreads();   // all warps done reading Bs
        if (tile + 1 < NTILES) {
#pragma unroll
            for (int i = 0; i < 4; i++) {
                uint32_t x = (uint32_t)(scode * 128 + (sq & 1) * 64 + i * 16);
                *(uint4*)(sdstb + SW128(x)) = pre[i];
            }
        }
        __syncthreads();   // Bs refilled
    }
}

// ---- exact rescore of candidates (bit-exact reference formula) ----
__global__ void __launch_bounds__(256) rescore_k(const float* __restrict__ emb,
                                                 int head) {
    __shared__ float rs[8][DD];
    const int wid = threadIdx.x >> 5, lane = threadIdx.x & 31;
    const int row = blockIdx.x * 8 + wid;

    ((float4*)rs[wid])[lane] = ((const float4*)(g_resid + (size_t)row * DD))[lane];
    __syncwarp();

    const float rn = g_rn[row];
    int cnt = g_ccnt[row];
    if (cnt > CAP) cnt = CAP;
    const float* __restrict__ Wb = emb + (size_t)head * KK * DD;
    const float* __restrict__ wnb = g_wn + head * KK;
    const float* __restrict__ r = rs[wid];

    float bsv = -3.4e38f;
    int bidx = 0x7fffffff;
    for (int ci = lane; ci < cnt; ci += 32) {
        int code = g_cand[row * CAP + ci];
        const float4* wp = (const float4*)(Wb + (size_t)code * DD);
        float acc = 0.0f;
#pragma unroll
        for (int i = 0; i < 32; i++) {       // sequential chain, k ascending
            float4 w = __ldg(&wp[i]);
            acc = __fmaf_rn(r[4 * i + 0], w.x, acc);
            acc = __fmaf_rn(r[4 * i + 1], w.y, acc);
            acc = __fmaf_rn(r[4 * i + 2], w.z, acc);
            acc = __fmaf_rn(r[4 * i + 3], w.w, acc);
        }
        float t1 = __fadd_rn(rn, wnb[code]);
        float s = -__fsub_rn(t1, __fmul_rn(2.0f, acc));
        if (s > bsv || (s == bsv && code < bidx)) { bsv = s; bidx = code; }
    }
#pragma unroll
    for (int off = 16; off; off >>= 1) {
        float os = __shfl_xor_sync(0xffffffffu, bsv, off);
        int   oi = __shfl_xor_sync(0xffffffffu, bidx, off);
        if (os > bsv || (os == bsv && oi < bidx)) { bsv = os; bidx = oi; }
    }
    if (lane == 0) g_sel[row] = (bidx == 0x7fffffff) ? 0 : bidx;
}

__global__ void update_k(const float* __restrict__ emb, int head) {
    const int b = blockIdx.x, d = threadIdx.x;
    const int idx = g_sel[b];
    const float w = emb[(size_t)head * KK * DD + (size_t)idx * DD + d];
    g_resid[b * DD + d] -= w;
    g_quant[b * DD + d] += w;
    if (d == 0) g_codes[b * HH + head] = idx;
}

__global__ void write_k(float* __restrict__ out,
                        int loss_off, int quant_off, int codes_off) {
    int i = blockIdx.x * blockDim.x + threadIdx.x;
    if (loss_off >= 0 && i < BB) out[loss_off + i] = 0.0f;
    if (quant_off >= 0 && i < BB * DD) out[quant_off + i] = g_quant[i];
    if (codes_off >= 0 && i < BB * HH) out[codes_off + i] = (float)g_codes[i];
}

extern "C" void kernel_launch(void* const* d_in, const int* in_sizes, int n_in,
                              void* d_out, int out_size) {
    const float* inputs = nullptr;
    const float* emb = nullptr;
    for (int i = 0; i < n_in; i++) {
        if (in_sizes[i] == BB * DD) inputs = (const float*)d_in[i];
        else if (in_sizes[i] == HH * KK * DD) emb = (const float*)d_in[i];
    }
    if (!inputs || !emb) { inputs = (const float*)d_in[0]; emb = (const float*)d_in[1]; }

    init_k<<<(BB * DD + 255) / 256, 256>>>(inputs);
    wn_k<<<(HH * KK) / 8, 256>>>(emb);
    wconv_k<<<(HH * KK * DD + 255) / 256, 256>>>(emb);

    for (int h = 0; h < HH; h++) {
        prep_k<<<BB / 8, 256>>>();
        dim3 grid(ROWTILES, NCSPLIT);
        mma_score_k<<<grid, 256>>>(h);
        rescore_k<<<BB / 8, 256>>>(emb, h);
        update_k<<<BB, DD>>>(emb, h);
    }

    int loss_off = -1, quant_off = -1, codes_off = -1;
    if (out_size == BB + BB * DD + BB * HH) {
        loss_off = 0; quant_off = BB; codes_off = BB + BB * DD;
    } else if (out_size == BB * DD) {
        quant_off = 0;
    } else if (out_size == BB * DD + BB * HH) {
        quant_off = 0; codes_off = BB * DD;
    } else if (out_size == BB + BB * DD) {
        loss_off = 0; quant_off = BB;
    } else {
        quant_off = 0;
    }
    write_k<<<(BB * DD + 255) / 256, 256>>>((float*)d_out,
                                            loss_off, quant_off, codes_off);
}